// round 12
// baseline (speedup 1.0000x reference)
#include <cuda_runtime.h>
#include <cuda_fp16.h>
#include <math.h>

#define N 4096
#define NN (4096ULL*4096ULL)
#define HROWS 2049            // stored spectral rows (hermitian half + nyquist)
#define TSTRIDE 2064          // padded row stride of transposed buffer

// ---------------- scratch ----------------
__device__ __half2 g_bufA[(size_t)HROWS * N];        // 33.6 MB: row-IFFT of hermitianized spectrum
__device__ __half2 g_bufB[(size_t)N * TSTRIDE];      // 33.8 MB: transposed [4096][2049(+pad)]
__device__ __half  g_imgh[NN];                       // 32 MB: spatial image * 4096 (fp16, TRANSPOSED)
__device__ float   g_c1[1365*1365];
__device__ float   g_c2[455*455];
__device__ float   g_c3[151*151];
__device__ float2  g_tw[4096];                       // W[k] = exp(+2*pi*i*k/4096), FULL table

// ---------------- complex helpers ----------------
__device__ __forceinline__ float2 cmul(float2 a, float2 b) {
    return make_float2(fmaf(a.x, b.x, -a.y * b.y), fmaf(a.x, b.y, a.y * b.x));
}
__device__ __forceinline__ float2 cadd(float2 a, float2 b) { return make_float2(a.x + b.x, a.y + b.y); }
__device__ __forceinline__ float2 csub(float2 a, float2 b) { return make_float2(a.x - b.x, a.y - b.y); }
__device__ __forceinline__ float2 cmuli(float2 z) { return make_float2(-z.y, z.x); }

__device__ __forceinline__ int SW(int i) { return i ^ ((i >> 4) & 15); }

// ---------------- fast atan2 ----------------
__device__ __forceinline__ float fast_atan2f(float y, float x)
{
    float ax = fabsf(x), ay = fabsf(y);
    float mx = fmaxf(ax, ay);
    float mn = fminf(ax, ay);
    float r  = __fdividef(mn, mx);
    float s  = r * r;
    float p  =             -0.0117212f;
    p = fmaf(p, s,  0.05265332f);
    p = fmaf(p, s, -0.11643287f);
    p = fmaf(p, s,  0.19354346f);
    p = fmaf(p, s, -0.33262347f);
    p = fmaf(p, s,  0.99997726f);
    float a = p * r;
    a = (ay > ax) ? (1.5707963267948966f - a) : a;
    a = (x < 0.0f) ? (3.1415926535897932f - a) : a;
    return (y < 0.0f) ? -a : a;
}

// ---------------- twiddle init (full 4096 table) ----------------
__global__ void twiddle_init() {
    int k = blockIdx.x * 1024 + threadIdx.x;
    float sp, cp;
    sincospif(2.0f * (float)k / 4096.0f, &sp, &cp);
    g_tw[k] = make_float2(cp, sp);
}

// ---------------- register radix-8 inverse butterfly (table twiddles) ----------------
template<bool TW>
__device__ __forceinline__ void bfly8(float2 x[8], int ps)
{
    const float R8 = 0.70710678118654752f;
    float2 w1, w2, w3, w4, w5, w6, w7;
    if (TW) {   // 7 independent loads; max index 7*511=3577 < 4096
        w1 = g_tw[ps];
        w2 = g_tw[2 * ps];
        w3 = g_tw[3 * ps];
        w4 = g_tw[4 * ps];
        w5 = g_tw[5 * ps];
        w6 = g_tw[6 * ps];
        w7 = g_tw[7 * ps];
    }
    float2 apc = cadd(x[0], x[4]), amc = csub(x[0], x[4]);
    float2 bpd = cadd(x[2], x[6]), bmd = csub(x[2], x[6]);
    float2 E0 = cadd(apc, bpd);
    float2 E1 = cadd(amc, cmuli(bmd));
    float2 E2 = csub(apc, bpd);
    float2 E3 = csub(amc, cmuli(bmd));

    float2 opc = cadd(x[1], x[5]), omc = csub(x[1], x[5]);
    float2 ppd = cadd(x[3], x[7]), pmd = csub(x[3], x[7]);
    float2 O0 = cadd(opc, ppd);
    float2 O1 = cadd(omc, cmuli(pmd));
    float2 O2 = csub(opc, ppd);
    float2 O3 = csub(omc, cmuli(pmd));

    float2 T1 = cmul(make_float2( R8, R8), O1);
    float2 T2 = cmuli(O2);
    float2 T3 = cmul(make_float2(-R8, R8), O3);

    x[0] = cadd(E0, O0); x[4] = csub(E0, O0);
    x[1] = cadd(E1, T1); x[5] = csub(E1, T1);
    x[2] = cadd(E2, T2); x[6] = csub(E2, T2);
    x[3] = cadd(E3, T3); x[7] = csub(E3, T3);

    if (TW) {
        x[1] = cmul(w1, x[1]); x[2] = cmul(w2, x[2]); x[3] = cmul(w3, x[3]);
        x[4] = cmul(w4, x[4]); x[5] = cmul(w5, x[5]); x[6] = cmul(w6, x[6]);
        x[7] = cmul(w7, x[7]);
    }
}

// ---------------- smem in-place stage ----------------
template<int S>
__device__ __forceinline__ void stage8_ip(float2* __restrict__ buf, int t)
{
    const int q  = t & (S - 1);
    const int ps = t - q;
    float2 x[8];
#pragma unroll
    for (int k = 0; k < 8; k++) x[k] = buf[SW(t + 512 * k)];
    bfly8<true>(x, ps);
    __syncthreads();
    const int ob = q + 8 * ps;
#pragma unroll
    for (int m = 0; m < 8; m++) buf[SW(ob + m * S)] = x[m];
    __syncthreads();
}

// elementwise spectrum math for one point
__device__ __forceinline__ float2 spec_point(float a, float b, float mkv, float pkv)
{
    float s2 = fmaf(a, a, b * b);
    float m = s2 * rsqrtf(fmaxf(s2, 1e-37f)) * mkv;
    float p = fast_atan2f(b, a) * pkv;
    float sp, cp;
    __sincosf(p, &sp, &cp);
    return make_float2(m * cp, m * sp);
}

// ---------------- pass 1: hermitianize (pair row 4096-r) + row IFFT, rows 0..2048 only ----------------
__global__ void __launch_bounds__(512, 3)
fft_pass1(const float* __restrict__ xr, const float* __restrict__ xi,
          const float* __restrict__ mk, const float* __restrict__ pk)
{
    extern __shared__ char smraw[];
    float2*  s0 = (float2*)smraw;             // 32 KB fp32 FFT buffer
    __half2* hz = (__half2*)(smraw + 32768);  // 16 KB: conj-reversed paired-row spectrum
    const int row = blockIdx.x;               // 0..2048
    const int rB  = (4096 - row) & 4095;      // paired row
    const int t   = threadIdx.x;

    const float4* xr4 = (const float4*)xr;
    const float4* xi4 = (const float4*)xi;
    const float4* mk4 = (const float4*)mk;
    const float4* pk4 = (const float4*)pk;

    // ---- phase A: row rB -> hz[(4096-idx)%4096] = conj(C_B[idx])  (fp16)
    {
        const int baseB = rB * (N / 4);
#pragma unroll
        for (int e = 0; e < 2; e++) {
            int i4 = t + 512 * e;
            float4 ar = xr4[baseB + i4];
            float4 br = xi4[baseB + i4];
            float4 mr = mk4[baseB + i4];
            float4 pr = pk4[baseB + i4];
            float av[4] = {ar.x, ar.y, ar.z, ar.w};
            float bv[4] = {br.x, br.y, br.z, br.w};
            float mv[4] = {mr.x, mr.y, mr.z, mr.w};
            float pv[4] = {pr.x, pr.y, pr.z, pr.w};
#pragma unroll
            for (int j = 0; j < 4; j++) {
                int idx = 4 * i4 + j;
                float2 c = spec_point(av[j], bv[j], mv[j], pv[j]);
                hz[(4096 - idx) & 4095] = __floats2half2_rn(c.x, -c.y);
            }
        }
    }
    __syncthreads();

    // ---- phase B: row `row` -> H = (C_A + hz)/2 into fp32 FFT buffer
    {
        const int baseA = row * (N / 4);
#pragma unroll
        for (int e = 0; e < 2; e++) {
            int i4 = t + 512 * e;
            float4 ar = xr4[baseA + i4];
            float4 br = xi4[baseA + i4];
            float4 mr = mk4[baseA + i4];
            float4 pr = pk4[baseA + i4];
            float av[4] = {ar.x, ar.y, ar.z, ar.w};
            float bv[4] = {br.x, br.y, br.z, br.w};
            float mv[4] = {mr.x, mr.y, mr.z, mr.w};
            float pv[4] = {pr.x, pr.y, pr.z, pr.w};
#pragma unroll
            for (int j = 0; j < 4; j++) {
                int idx = 4 * i4 + j;
                float2 c = spec_point(av[j], bv[j], mv[j], pv[j]);
                float2 z = __half22float2(hz[idx]);
                s0[SW(idx)] = make_float2(0.5f * (c.x + z.x), 0.5f * (c.y + z.y));
            }
        }
    }
    __syncthreads();

    stage8_ip<1>(s0, t);
    stage8_ip<8>(s0, t);
    stage8_ip<64>(s0, t);

    float2 x[8];
#pragma unroll
    for (int k = 0; k < 8; k++) x[k] = s0[SW(t + 512 * k)];
    bfly8<false>(x, 0);
    const size_t base = (size_t)row * N;
#pragma unroll
    for (int m = 0; m < 8; m++)
        g_bufA[base + t + 512 * m] = __float22half2_rn(x[m]);
}

// ---------------- fp16 transpose: [2049][4096] -> [4096][TSTRIDE] ----------------
__global__ void __launch_bounds__(256)
transpose_c()
{
    __shared__ __half2 tile[32][33];
    int x  = blockIdx.x * 32 + threadIdx.x;   // input col
    int y0 = blockIdx.y * 32;                 // input row base
#pragma unroll
    for (int j = threadIdx.y; j < 32; j += 8) {
        int r = y0 + j;
        if (r < HROWS)
            tile[j][threadIdx.x] = g_bufA[(size_t)r * N + x];
    }
    __syncthreads();
    int x2 = blockIdx.y * 32 + threadIdx.x;   // output col (= input row)
    int y2 = blockIdx.x * 32;                 // output row base (= input col)
#pragma unroll
    for (int j = threadIdx.y; j < 32; j += 8) {
        if (x2 < HROWS)
            g_bufB[(size_t)(y2 + j) * TSTRIDE + x2] = tile[threadIdx.x][j];
    }
}

// ---------------- pass 2: hermitian columns, two per FFT, direct mirrored gmem reads ----------------
__global__ void __launch_bounds__(512, 3)
fft_pass2()
{
    extern __shared__ float2 sm[];
    float2* s0 = sm;                               // 32 KB fp32 FFT buffer
    const int p = blockIdx.x;                      // column pair: n2 = 2p, 2p+1
    const int t = threadIdx.x;

    const __half2* rowB1 = g_bufB + (size_t)(2 * p)     * TSTRIDE;
    const __half2* rowB2 = g_bufB + (size_t)(2 * p + 1) * TSTRIDE;

    float2 x[8];
#pragma unroll
    for (int k = 0; k < 8; k++) {
        int idx = t + 512 * k;
        float2 z1, z2;
        if (idx <= 2048) {
            z1 = __half22float2(rowB1[idx]);
            z2 = __half22float2(rowB2[idx]);
        } else {
            int ridx = 4096 - idx;
            z1 = __half22float2(rowB1[ridx]); z1.y = -z1.y;
            z2 = __half22float2(rowB2[ridx]); z2.y = -z2.y;
        }
        x[k] = make_float2(z1.x - z2.y, z1.y + z2.x);
    }
    bfly8<true>(x, t);
#pragma unroll
    for (int m = 0; m < 8; m++) s0[SW(8 * t + m)] = x[m];
    __syncthreads();

    stage8_ip<8>(s0, t);
    stage8_ip<64>(s0, t);

#pragma unroll
    for (int k = 0; k < 8; k++) x[k] = s0[SW(t + 512 * k)];
    bfly8<false>(x, 0);
    // store img*4096: scale = 4096/N^2 = 1/4096, sign (-1)^(n1+n2) with n1=t+512m (even stride)
    const float scale = 1.0f / 4096.0f;
    const float sg = (t & 1) ? -scale : scale;
    const size_t base1 = (size_t)(2 * p)     * N;
    const size_t base2 = (size_t)(2 * p + 1) * N;
#pragma unroll
    for (int m = 0; m < 8; m++) {
        int n = t + 512 * m;
        g_imgh[base1 + n] = __float2half(x[m].x * sg);
        g_imgh[base2 + n] = __float2half(x[m].y * -sg);
    }
}

// ---------------- conv 3x3 stride 3 + bias + BN + PReLU (templated input type) ----------------
template<typename T>
__device__ __forceinline__ float conv_point_t(const T* __restrict__ in, int Win,
                                              int i, int j, const float* w,
                                              float cb, float sc, float sh, float al)
{
    const T* r0 = in + (size_t)(3 * i) * Win + 3 * j;
    float acc = 0.0f;
#pragma unroll
    for (int dy = 0; dy < 3; dy++)
#pragma unroll
        for (int dx = 0; dx < 3; dx++)
            acc = fmaf((float)r0[(size_t)dy * Win + dx], w[dy * 3 + dx], acc);
    acc += cb;
    acc = fmaf(acc, sc, sh);
    return (acc >= 0.0f) ? acc : al * acc;
}

template<typename T>
__global__ void __launch_bounds__(256)
conv_bn_prelu(const T* __restrict__ in, float* __restrict__ out,
              int Win, int Wout, int Hout,
              const float* __restrict__ cw, const float* __restrict__ cb,
              const float* __restrict__ bg, const float* __restrict__ bb,
              const float* __restrict__ bm, const float* __restrict__ bv,
              const float* __restrict__ pa, int layer, float wscale)
{
    int j = blockIdx.x * blockDim.x + threadIdx.x;
    int i = blockIdx.y * blockDim.y + threadIdx.y;
    if (i >= Hout || j >= Wout) return;
    const float* wb = cw + layer * 9;
    float w[9];
#pragma unroll
    for (int dy = 0; dy < 3; dy++)
#pragma unroll
        for (int dx = 0; dx < 3; dx++)
            w[dy * 3 + dx] = __ldg(&wb[dx * 3 + dy]) * wscale;   // transposed weight
    float rs = rsqrtf(__ldg(&bv[layer]) + 1e-5f);
    float gg = __ldg(&bg[layer]);
    float sc = gg * rs;
    float sh = __ldg(&bb[layer]) - gg * __ldg(&bm[layer]) * rs;
    out[(size_t)i * Wout + j] =
        conv_point_t<T>(in, Win, i, j, w, __ldg(&cb[layer]), sc, sh, __ldg(&pa[layer]));
}

// ---------------- fused tail ----------------
__global__ void __launch_bounds__(256, 1)
tail_kernel(const float* __restrict__ c3,
            const float* __restrict__ cw, const float* __restrict__ cbv,
            const float* __restrict__ bg, const float* __restrict__ bb,
            const float* __restrict__ bm, const float* __restrict__ bv,
            const float* __restrict__ pa,
            const float* __restrict__ fc5w, const float* __restrict__ fc5b,
            const float* __restrict__ lng,  const float* __restrict__ lnb,
            const float* __restrict__ p5a,
            const float* __restrict__ fc6w, const float* __restrict__ fc6b,
            float* __restrict__ out)
{
    __shared__ float c4s[2500];
    __shared__ float c5s[256];
    __shared__ float h[82];
    __shared__ float mu_s, rstd_s;
    const int t = threadIdx.x;

    {
        const int layer = 3;
        float w[9];
#pragma unroll
        for (int dy = 0; dy < 3; dy++)
#pragma unroll
            for (int dx = 0; dx < 3; dx++)
                w[dy * 3 + dx] = cw[layer * 9 + dx * 3 + dy];
        float rs = rsqrtf(bv[layer] + 1e-5f);
        float sc = bg[layer] * rs;
        float sh = bb[layer] - bg[layer] * bm[layer] * rs;
        for (int o = t; o < 2500; o += 256) {
            int i = o / 50, j = o % 50;
            c4s[o] = conv_point_t<float>(c3, 151, i, j, w, cbv[layer], sc, sh, pa[layer]);
        }
    }
    __syncthreads();

    {
        const int layer = 4;
        float w[9];
#pragma unroll
        for (int dy = 0; dy < 3; dy++)
#pragma unroll
            for (int dx = 0; dx < 3; dx++)
                w[dy * 3 + dx] = cw[layer * 9 + dx * 3 + dy];
        float rs = rsqrtf(bv[layer] + 1e-5f);
        float sc = bg[layer] * rs;
        float sh = bb[layer] - bg[layer] * bm[layer] * rs;
        if (t < 256) {
            int i = t >> 4, j = t & 15;
            c5s[t] = conv_point_t<float>(c4s, 50, i, j, w, cbv[layer], sc, sh, pa[layer]);
        }
    }
    __syncthreads();

    for (int o = t; o < 82; o += 256) {
        float acc = fc5b[o];
        for (int v = 0; v < 256; v++) {
            int i = v >> 4, j = v & 15;
            acc = fmaf(c5s[j * 16 + i], fc5w[v * 82 + o], acc);
        }
        h[o] = acc;
    }
    __syncthreads();
    if (t == 0) {
        float mu = 0.0f;
        for (int o = 0; o < 82; o++) mu += h[o];
        mu *= (1.0f / 82.0f);
        float var = 0.0f;
        for (int o = 0; o < 82; o++) { float dd = h[o] - mu; var = fmaf(dd, dd, var); }
        var *= (1.0f / 82.0f);
        mu_s = mu;
        rstd_s = rsqrtf(var + 1e-5f);
    }
    __syncthreads();
    if (t < 5) {
        float alpha = p5a[0];
        float acc = fc6b[t];
        for (int k = 0; k < 82; k++) {
            float v = (h[k] - mu_s) * rstd_s * lng[k] + lnb[k];
            v = (v >= 0.0f) ? v : alpha * v;
            acc = fmaf(v, fc6w[k * 5 + t], acc);
        }
        out[t] = acc;
    }
}

// ---------------- launch ----------------
extern "C" void kernel_launch(void* const* d_in, const int* in_sizes, int n_in,
                              void* d_out, int out_size)
{
    const float* xr    = (const float*)d_in[0];
    const float* xi    = (const float*)d_in[1];
    const float* mk    = (const float*)d_in[2];
    const float* pk    = (const float*)d_in[3];
    const float* convw = (const float*)d_in[4];
    const float* convb = (const float*)d_in[5];
    const float* bng   = (const float*)d_in[6];
    const float* bnb   = (const float*)d_in[7];
    const float* bnm   = (const float*)d_in[8];
    const float* bnv   = (const float*)d_in[9];
    const float* pra   = (const float*)d_in[10];
    const float* fc5w  = (const float*)d_in[11];
    const float* fc5b  = (const float*)d_in[12];
    const float* lng   = (const float*)d_in[13];
    const float* lnb   = (const float*)d_in[14];
    const float* p5a   = (const float*)d_in[15];
    const float* fc6w  = (const float*)d_in[16];
    const float* fc6b  = (const float*)d_in[17];
    float* out = (float*)d_out;

    cudaFuncSetAttribute(fft_pass1, cudaFuncAttributeMaxDynamicSharedMemorySize, 49152);
    cudaFuncSetAttribute(fft_pass2, cudaFuncAttributeMaxDynamicSharedMemorySize, 32768);

    __half* imgh;
    float *c1, *c2, *c3;
    cudaGetSymbolAddress((void**)&imgh, g_imgh);
    cudaGetSymbolAddress((void**)&c1,  g_c1);
    cudaGetSymbolAddress((void**)&c2,  g_c2);
    cudaGetSymbolAddress((void**)&c3,  g_c3);

    twiddle_init<<<4, 1024>>>();
    fft_pass1<<<HROWS, 512, 49152>>>(xr, xi, mk, pk);
    transpose_c<<<dim3(128, 65), dim3(32, 8)>>>();
    fft_pass2<<<2048, 512, 32768>>>();

    dim3 cb(32, 8);
    conv_bn_prelu<__half><<<dim3((1365 + 31) / 32, (1365 + 7) / 8), cb>>>(imgh, c1, 4096, 1365, 1365,
        convw, convb, bng, bnb, bnm, bnv, pra, 0, 1.0f / 4096.0f);
    conv_bn_prelu<float><<<dim3((455 + 31) / 32, (455 + 7) / 8), cb>>>(c1, c2, 1365, 455, 455,
        convw, convb, bng, bnb, bnm, bnv, pra, 1, 1.0f);
    conv_bn_prelu<float><<<dim3((151 + 31) / 32, (151 + 7) / 8), cb>>>(c2, c3, 455, 151, 151,
        convw, convb, bng, bnb, bnm, bnv, pra, 2, 1.0f);

    tail_kernel<<<1, 256>>>(c3, convw, convb, bng, bnb, bnm, bnv, pra,
                            fc5w, fc5b, lng, lnb, p5a, fc6w, fc6b, out);
}

// round 13
// speedup vs baseline: 1.0738x; 1.0738x over previous
#include <cuda_runtime.h>
#include <cuda_fp16.h>
#include <math.h>

#define N 4096
#define NN (4096ULL*4096ULL)
#define HROWS 2049            // stored spectral rows (hermitian half + nyquist)
#define TSTRIDE 2064          // padded row stride of transposed buffer

// ---------------- scratch ----------------
__device__ __half2 g_bufA[(size_t)HROWS * N];        // 33.6 MB: row-IFFT of hermitianized spectrum
__device__ __half2 g_bufB[(size_t)N * TSTRIDE];      // 33.8 MB: transposed [4096][2049(+pad)]
__device__ __half  g_imgh[NN];                       // 32 MB: spatial image * 4096 (fp16, TRANSPOSED)
__device__ float   g_c1[1365*1365];
__device__ float   g_c2[455*455];
__device__ float   g_c3[151*151];
__device__ float2  g_tw[1024];                       // W[k] = exp(+2*pi*i*k/4096)

// ---------------- complex helpers ----------------
__device__ __forceinline__ float2 cmul(float2 a, float2 b) {
    return make_float2(fmaf(a.x, b.x, -a.y * b.y), fmaf(a.x, b.y, a.y * b.x));
}
__device__ __forceinline__ float2 cadd(float2 a, float2 b) { return make_float2(a.x + b.x, a.y + b.y); }
__device__ __forceinline__ float2 csub(float2 a, float2 b) { return make_float2(a.x - b.x, a.y - b.y); }
__device__ __forceinline__ float2 cmuli(float2 z) { return make_float2(-z.y, z.x); }

__device__ __forceinline__ int SW(int i) { return i ^ ((i >> 4) & 15); }

// ---------------- fast atan2 ----------------
__device__ __forceinline__ float fast_atan2f(float y, float x)
{
    float ax = fabsf(x), ay = fabsf(y);
    float mx = fmaxf(ax, ay);
    float mn = fminf(ax, ay);
    float r  = __fdividef(mn, mx);
    float s  = r * r;
    float p  =             -0.0117212f;
    p = fmaf(p, s,  0.05265332f);
    p = fmaf(p, s, -0.11643287f);
    p = fmaf(p, s,  0.19354346f);
    p = fmaf(p, s, -0.33262347f);
    p = fmaf(p, s,  0.99997726f);
    float a = p * r;
    a = (ay > ax) ? (1.5707963267948966f - a) : a;
    a = (x < 0.0f) ? (3.1415926535897932f - a) : a;
    return (y < 0.0f) ? -a : a;
}

// ---------------- twiddle init ----------------
__global__ void twiddle_init() {
    int k = threadIdx.x;
    float sp, cp;
    sincospif(2.0f * (float)k / 4096.0f, &sp, &cp);
    g_tw[k] = make_float2(cp, sp);
}

// ---------------- register radix-8 inverse butterfly (serial twiddle chain) ----------------
template<bool TW>
__device__ __forceinline__ void bfly8(float2 x[8], int ps)
{
    const float R8 = 0.70710678118654752f;
    float2 apc = cadd(x[0], x[4]), amc = csub(x[0], x[4]);
    float2 bpd = cadd(x[2], x[6]), bmd = csub(x[2], x[6]);
    float2 E0 = cadd(apc, bpd);
    float2 E1 = cadd(amc, cmuli(bmd));
    float2 E2 = csub(apc, bpd);
    float2 E3 = csub(amc, cmuli(bmd));

    float2 opc = cadd(x[1], x[5]), omc = csub(x[1], x[5]);
    float2 ppd = cadd(x[3], x[7]), pmd = csub(x[3], x[7]);
    float2 O0 = cadd(opc, ppd);
    float2 O1 = cadd(omc, cmuli(pmd));
    float2 O2 = csub(opc, ppd);
    float2 O3 = csub(omc, cmuli(pmd));

    float2 T1 = cmul(make_float2( R8, R8), O1);
    float2 T2 = cmuli(O2);
    float2 T3 = cmul(make_float2(-R8, R8), O3);

    x[0] = cadd(E0, O0); x[4] = csub(E0, O0);
    x[1] = cadd(E1, T1); x[5] = csub(E1, T1);
    x[2] = cadd(E2, T2); x[6] = csub(E2, T2);
    x[3] = cadd(E3, T3); x[7] = csub(E3, T3);

    if (TW) {
        float2 w1 = g_tw[ps];
        float2 w2 = cmul(w1, w1);
        float2 w3 = cmul(w2, w1);
        float2 w4 = cmul(w2, w2);
        float2 w5 = cmul(w3, w2);
        float2 w6 = cmul(w3, w3);
        float2 w7 = cmul(w4, w3);
        x[1] = cmul(w1, x[1]); x[2] = cmul(w2, x[2]); x[3] = cmul(w3, x[3]);
        x[4] = cmul(w4, x[4]); x[5] = cmul(w5, x[5]); x[6] = cmul(w6, x[6]);
        x[7] = cmul(w7, x[7]);
    }
}

// ---------------- smem in-place stage ----------------
template<int S>
__device__ __forceinline__ void stage8_ip(float2* __restrict__ buf, int t)
{
    const int q  = t & (S - 1);
    const int ps = t - q;
    float2 x[8];
#pragma unroll
    for (int k = 0; k < 8; k++) x[k] = buf[SW(t + 512 * k)];
    bfly8<true>(x, ps);
    __syncthreads();
    const int ob = q + 8 * ps;
#pragma unroll
    for (int m = 0; m < 8; m++) buf[SW(ob + m * S)] = x[m];
    __syncthreads();
}

// elementwise spectrum math for one point
__device__ __forceinline__ float2 spec_point(float a, float b, float mkv, float pkv)
{
    float s2 = fmaf(a, a, b * b);
    float m = s2 * rsqrtf(fmaxf(s2, 1e-37f)) * mkv;
    float p = fast_atan2f(b, a) * pkv;
    float sp, cp;
    __sincosf(p, &sp, &cp);
    return make_float2(m * cp, m * sp);
}

// ---------------- pass 1: hermitianize (pair row 4096-r) + row IFFT, rows 0..2048 only ----------------
__global__ void __launch_bounds__(512, 3)
fft_pass1(const float* __restrict__ xr, const float* __restrict__ xi,
          const float* __restrict__ mk, const float* __restrict__ pk)
{
    extern __shared__ char smraw[];
    float2*  s0 = (float2*)smraw;             // 32 KB fp32 FFT buffer
    __half2* hz = (__half2*)(smraw + 32768);  // 16 KB: conj-reversed paired-row spectrum
    const int row = blockIdx.x;               // 0..2048
    const int rB  = (4096 - row) & 4095;      // paired row
    const int t   = threadIdx.x;

    const float4* xr4 = (const float4*)xr;
    const float4* xi4 = (const float4*)xi;
    const float4* mk4 = (const float4*)mk;
    const float4* pk4 = (const float4*)pk;

    // ---- phase A: row rB -> hz[(4096-idx)%4096] = conj(C_B[idx])  (fp16)
    {
        const int baseB = rB * (N / 4);
#pragma unroll
        for (int e = 0; e < 2; e++) {
            int i4 = t + 512 * e;
            float4 ar = xr4[baseB + i4];
            float4 br = xi4[baseB + i4];
            float4 mr = mk4[baseB + i4];
            float4 pr = pk4[baseB + i4];
            float av[4] = {ar.x, ar.y, ar.z, ar.w};
            float bv[4] = {br.x, br.y, br.z, br.w};
            float mv[4] = {mr.x, mr.y, mr.z, mr.w};
            float pv[4] = {pr.x, pr.y, pr.z, pr.w};
#pragma unroll
            for (int j = 0; j < 4; j++) {
                int idx = 4 * i4 + j;
                float2 c = spec_point(av[j], bv[j], mv[j], pv[j]);
                hz[(4096 - idx) & 4095] = __floats2half2_rn(c.x, -c.y);
            }
        }
    }
    __syncthreads();

    // ---- phase B: row `row` -> H = (C_A + hz)/2 into fp32 FFT buffer
    {
        const int baseA = row * (N / 4);
#pragma unroll
        for (int e = 0; e < 2; e++) {
            int i4 = t + 512 * e;
            float4 ar = xr4[baseA + i4];
            float4 br = xi4[baseA + i4];
            float4 mr = mk4[baseA + i4];
            float4 pr = pk4[baseA + i4];
            float av[4] = {ar.x, ar.y, ar.z, ar.w};
            float bv[4] = {br.x, br.y, br.z, br.w};
            float mv[4] = {mr.x, mr.y, mr.z, mr.w};
            float pv[4] = {pr.x, pr.y, pr.z, pr.w};
#pragma unroll
            for (int j = 0; j < 4; j++) {
                int idx = 4 * i4 + j;
                float2 c = spec_point(av[j], bv[j], mv[j], pv[j]);
                float2 z = __half22float2(hz[idx]);
                s0[SW(idx)] = make_float2(0.5f * (c.x + z.x), 0.5f * (c.y + z.y));
            }
        }
    }
    __syncthreads();

    stage8_ip<1>(s0, t);
    stage8_ip<8>(s0, t);
    stage8_ip<64>(s0, t);

    float2 x[8];
#pragma unroll
    for (int k = 0; k < 8; k++) x[k] = s0[SW(t + 512 * k)];
    bfly8<false>(x, 0);
    const size_t base = (size_t)row * N;
#pragma unroll
    for (int m = 0; m < 8; m++)
        g_bufA[base + t + 512 * m] = __float22half2_rn(x[m]);
}

// ---------------- fp16 transpose: [2049][4096] -> [4096][TSTRIDE] ----------------
__global__ void __launch_bounds__(256)
transpose_c()
{
    __shared__ __half2 tile[32][33];
    int x  = blockIdx.x * 32 + threadIdx.x;   // input col
    int y0 = blockIdx.y * 32;                 // input row base
#pragma unroll
    for (int j = threadIdx.y; j < 32; j += 8) {
        int r = y0 + j;
        if (r < HROWS)
            tile[j][threadIdx.x] = g_bufA[(size_t)r * N + x];
    }
    __syncthreads();
    int x2 = blockIdx.y * 32 + threadIdx.x;   // output col (= input row)
    int y2 = blockIdx.x * 32;                 // output row base (= input col)
#pragma unroll
    for (int j = threadIdx.y; j < 32; j += 8) {
        if (x2 < HROWS)
            g_bufB[(size_t)(y2 + j) * TSTRIDE + x2] = tile[threadIdx.x][j];
    }
}

// ---------------- pass 2: hermitian columns, two per FFT (R11 smem-staged version) ----------------
__global__ void __launch_bounds__(512, 3)
fft_pass2()
{
    extern __shared__ char smraw[];
    float2*  s0  = (float2*)smraw;                 // 32 KB fp32 FFT buffer
    __half2* hz1 = (__half2*)(smraw + 32768);      // 2049 entries
    __half2* hz2 = hz1 + 2052;                     // 2049 entries (padded offset)
    const int p = blockIdx.x;                      // column pair: n2 = 2p, 2p+1
    const int t = threadIdx.x;

    const __half2* rowB1 = g_bufB + (size_t)(2 * p)     * TSTRIDE;
    const __half2* rowB2 = g_bufB + (size_t)(2 * p + 1) * TSTRIDE;
    for (int idx = t; idx < HROWS; idx += 512) {
        hz1[idx] = rowB1[idx];
        hz2[idx] = rowB2[idx];
    }
    __syncthreads();

    float2 x[8];
#pragma unroll
    for (int k = 0; k < 8; k++) {
        int idx = t + 512 * k;
        float2 z1, z2;
        if (idx <= 2048) {
            z1 = __half22float2(hz1[idx]);
            z2 = __half22float2(hz2[idx]);
        } else {
            int ridx = 4096 - idx;
            z1 = __half22float2(hz1[ridx]); z1.y = -z1.y;
            z2 = __half22float2(hz2[ridx]); z2.y = -z2.y;
        }
        x[k] = make_float2(z1.x - z2.y, z1.y + z2.x);
    }
    bfly8<true>(x, t);
    __syncthreads();
#pragma unroll
    for (int m = 0; m < 8; m++) s0[SW(8 * t + m)] = x[m];
    __syncthreads();

    stage8_ip<8>(s0, t);
    stage8_ip<64>(s0, t);

#pragma unroll
    for (int k = 0; k < 8; k++) x[k] = s0[SW(t + 512 * k)];
    bfly8<false>(x, 0);
    const float scale = 1.0f / 4096.0f;
    const float sg = (t & 1) ? -scale : scale;
    const size_t base1 = (size_t)(2 * p)     * N;
    const size_t base2 = (size_t)(2 * p + 1) * N;
#pragma unroll
    for (int m = 0; m < 8; m++) {
        int n = t + 512 * m;
        g_imgh[base1 + n] = __float2half(x[m].x * sg);
        g_imgh[base2 + n] = __float2half(x[m].y * -sg);
    }
}

// ---------------- conv1 (half input, half2-vectorized, 2 outputs/thread) ----------------
__global__ void __launch_bounds__(256)
conv1_h2(const __half* __restrict__ in, float* __restrict__ out,
         const float* __restrict__ cw, const float* __restrict__ cb,
         const float* __restrict__ bg, const float* __restrict__ bb,
         const float* __restrict__ bm, const float* __restrict__ bv,
         const float* __restrict__ pa, float wscale)
{
    const int Win = 4096, Wout = 1365, Hout = 1365;
    int u = blockIdx.x * blockDim.x + threadIdx.x;   // output pair index
    int i = blockIdx.y * blockDim.y + threadIdx.y;
    int j0 = 2 * u;
    if (i >= Hout || j0 >= Wout) return;
    float w[9];
#pragma unroll
    for (int dy = 0; dy < 3; dy++)
#pragma unroll
        for (int dx = 0; dx < 3; dx++)
            w[dy * 3 + dx] = __ldg(&cw[dx * 3 + dy]) * wscale;   // transposed weight, layer 0
    float rs = rsqrtf(__ldg(&bv[0]) + 1e-5f);
    float gg = __ldg(&bg[0]);
    float sc = gg * rs;
    float sh = __ldg(&bb[0]) - gg * __ldg(&bm[0]) * rs;
    float cbv = __ldg(&cb[0]);
    float al  = __ldg(&pa[0]);

    // input cols 6u .. 6u+5 (6u even, aligned half2), rows 3i..3i+2
    const __half2* base = (const __half2*)(in + (size_t)(3 * i) * Win) + 3 * u;
    float acc0 = 0.0f, acc1 = 0.0f;
#pragma unroll
    for (int dy = 0; dy < 3; dy++) {
        const __half2* r = base + (size_t)dy * (Win / 2);
        float2 p0 = __half22float2(r[0]);   // cols 6u, 6u+1
        float2 p1 = __half22float2(r[1]);   // cols 6u+2, 6u+3
        float2 p2 = __half22float2(r[2]);   // cols 6u+4, 6u+5
        acc0 = fmaf(p0.x, w[dy*3+0], acc0);
        acc0 = fmaf(p0.y, w[dy*3+1], acc0);
        acc0 = fmaf(p1.x, w[dy*3+2], acc0);
        acc1 = fmaf(p1.y, w[dy*3+0], acc1);
        acc1 = fmaf(p2.x, w[dy*3+1], acc1);
        acc1 = fmaf(p2.y, w[dy*3+2], acc1);
    }
    acc0 = fmaf(acc0 + cbv, sc, sh);
    acc1 = fmaf(acc1 + cbv, sc, sh);
    acc0 = (acc0 >= 0.0f) ? acc0 : al * acc0;
    acc1 = (acc1 >= 0.0f) ? acc1 : al * acc1;
    size_t ob = (size_t)i * Wout + j0;
    out[ob] = acc0;
    if (j0 + 1 < Wout) out[ob + 1] = acc1;
}

// ---------------- generic conv 3x3 stride 3 + bias + BN + PReLU (fp32 input) ----------------
__device__ __forceinline__ float conv_point(const float* __restrict__ in, int Win,
                                            int i, int j, const float* w,
                                            float cb, float sc, float sh, float al)
{
    const float* r0 = in + (size_t)(3 * i) * Win + 3 * j;
    float acc = 0.0f;
#pragma unroll
    for (int dy = 0; dy < 3; dy++)
#pragma unroll
        for (int dx = 0; dx < 3; dx++)
            acc = fmaf(r0[(size_t)dy * Win + dx], w[dy * 3 + dx], acc);
    acc += cb;
    acc = fmaf(acc, sc, sh);
    return (acc >= 0.0f) ? acc : al * acc;
}

__global__ void __launch_bounds__(256)
conv_bn_prelu(const float* __restrict__ in, float* __restrict__ out,
              int Win, int Wout, int Hout,
              const float* __restrict__ cw, const float* __restrict__ cb,
              const float* __restrict__ bg, const float* __restrict__ bb,
              const float* __restrict__ bm, const float* __restrict__ bv,
              const float* __restrict__ pa, int layer)
{
    int j = blockIdx.x * blockDim.x + threadIdx.x;
    int i = blockIdx.y * blockDim.y + threadIdx.y;
    if (i >= Hout || j >= Wout) return;
    const float* wb = cw + layer * 9;
    float w[9];
#pragma unroll
    for (int dy = 0; dy < 3; dy++)
#pragma unroll
        for (int dx = 0; dx < 3; dx++)
            w[dy * 3 + dx] = __ldg(&wb[dx * 3 + dy]);   // transposed weight
    float rs = rsqrtf(__ldg(&bv[layer]) + 1e-5f);
    float gg = __ldg(&bg[layer]);
    float sc = gg * rs;
    float sh = __ldg(&bb[layer]) - gg * __ldg(&bm[layer]) * rs;
    out[(size_t)i * Wout + j] =
        conv_point(in, Win, i, j, w, __ldg(&cb[layer]), sc, sh, __ldg(&pa[layer]));
}

// ---------------- fused tail ----------------
__global__ void __launch_bounds__(256, 1)
tail_kernel(const float* __restrict__ c3,
            const float* __restrict__ cw, const float* __restrict__ cbv,
            const float* __restrict__ bg, const float* __restrict__ bb,
            const float* __restrict__ bm, const float* __restrict__ bv,
            const float* __restrict__ pa,
            const float* __restrict__ fc5w, const float* __restrict__ fc5b,
            const float* __restrict__ lng,  const float* __restrict__ lnb,
            const float* __restrict__ p5a,
            const float* __restrict__ fc6w, const float* __restrict__ fc6b,
            float* __restrict__ out)
{
    __shared__ float c4s[2500];
    __shared__ float c5s[256];
    __shared__ float h[82];
    __shared__ float mu_s, rstd_s;
    const int t = threadIdx.x;

    {
        const int layer = 3;
        float w[9];
#pragma unroll
        for (int dy = 0; dy < 3; dy++)
#pragma unroll
            for (int dx = 0; dx < 3; dx++)
                w[dy * 3 + dx] = cw[layer * 9 + dx * 3 + dy];
        float rs = rsqrtf(bv[layer] + 1e-5f);
        float sc = bg[layer] * rs;
        float sh = bb[layer] - bg[layer] * bm[layer] * rs;
        for (int o = t; o < 2500; o += 256) {
            int i = o / 50, j = o % 50;
            c4s[o] = conv_point(c3, 151, i, j, w, cbv[layer], sc, sh, pa[layer]);
        }
    }
    __syncthreads();

    {
        const int layer = 4;
        float w[9];
#pragma unroll
        for (int dy = 0; dy < 3; dy++)
#pragma unroll
            for (int dx = 0; dx < 3; dx++)
                w[dy * 3 + dx] = cw[layer * 9 + dx * 3 + dy];
        float rs = rsqrtf(bv[layer] + 1e-5f);
        float sc = bg[layer] * rs;
        float sh = bb[layer] - bg[layer] * bm[layer] * rs;
        if (t < 256) {
            int i = t >> 4, j = t & 15;
            c5s[t] = conv_point(c4s, 50, i, j, w, cbv[layer], sc, sh, pa[layer]);
        }
    }
    __syncthreads();

    for (int o = t; o < 82; o += 256) {
        float acc = fc5b[o];
        for (int v = 0; v < 256; v++) {
            int i = v >> 4, j = v & 15;
            acc = fmaf(c5s[j * 16 + i], fc5w[v * 82 + o], acc);
        }
        h[o] = acc;
    }
    __syncthreads();
    if (t == 0) {
        float mu = 0.0f;
        for (int o = 0; o < 82; o++) mu += h[o];
        mu *= (1.0f / 82.0f);
        float var = 0.0f;
        for (int o = 0; o < 82; o++) { float dd = h[o] - mu; var = fmaf(dd, dd, var); }
        var *= (1.0f / 82.0f);
        mu_s = mu;
        rstd_s = rsqrtf(var + 1e-5f);
    }
    __syncthreads();
    if (t < 5) {
        float alpha = p5a[0];
        float acc = fc6b[t];
        for (int k = 0; k < 82; k++) {
            float v = (h[k] - mu_s) * rstd_s * lng[k] + lnb[k];
            v = (v >= 0.0f) ? v : alpha * v;
            acc = fmaf(v, fc6w[k * 5 + t], acc);
        }
        out[t] = acc;
    }
}

// ---------------- launch ----------------
extern "C" void kernel_launch(void* const* d_in, const int* in_sizes, int n_in,
                              void* d_out, int out_size)
{
    const float* xr    = (const float*)d_in[0];
    const float* xi    = (const float*)d_in[1];
    const float* mk    = (const float*)d_in[2];
    const float* pk    = (const float*)d_in[3];
    const float* convw = (const float*)d_in[4];
    const float* convb = (const float*)d_in[5];
    const float* bng   = (const float*)d_in[6];
    const float* bnb   = (const float*)d_in[7];
    const float* bnm   = (const float*)d_in[8];
    const float* bnv   = (const float*)d_in[9];
    const float* pra   = (const float*)d_in[10];
    const float* fc5w  = (const float*)d_in[11];
    const float* fc5b  = (const float*)d_in[12];
    const float* lng   = (const float*)d_in[13];
    const float* lnb   = (const float*)d_in[14];
    const float* p5a   = (const float*)d_in[15];
    const float* fc6w  = (const float*)d_in[16];
    const float* fc6b  = (const float*)d_in[17];
    float* out = (float*)d_out;

    cudaFuncSetAttribute(fft_pass1, cudaFuncAttributeMaxDynamicSharedMemorySize, 49152);
    cudaFuncSetAttribute(fft_pass2, cudaFuncAttributeMaxDynamicSharedMemorySize, 49184);

    __half* imgh;
    float *c1, *c2, *c3;
    cudaGetSymbolAddress((void**)&imgh, g_imgh);
    cudaGetSymbolAddress((void**)&c1,  g_c1);
    cudaGetSymbolAddress((void**)&c2,  g_c2);
    cudaGetSymbolAddress((void**)&c3,  g_c3);

    twiddle_init<<<1, 1024>>>();
    fft_pass1<<<HROWS, 512, 49152>>>(xr, xi, mk, pk);
    transpose_c<<<dim3(128, 65), dim3(32, 8)>>>();
    fft_pass2<<<2048, 512, 49184>>>();

    dim3 cb(32, 8);
    conv1_h2<<<dim3((683 + 31) / 32, (1365 + 7) / 8), cb>>>(imgh, c1,
        convw, convb, bng, bnb, bnm, bnv, pra, 1.0f / 4096.0f);
    conv_bn_prelu<<<dim3((455 + 31) / 32, (455 + 7) / 8), cb>>>(c1, c2, 1365, 455, 455,
        convw, convb, bng, bnb, bnm, bnv, pra, 1);
    conv_bn_prelu<<<dim3((151 + 31) / 32, (151 + 7) / 8), cb>>>(c2, c3, 455, 151, 151,
        convw, convb, bng, bnb, bnm, bnv, pra, 2);

    tail_kernel<<<1, 256>>>(c3, convw, convb, bng, bnb, bnm, bnv, pra,
                            fc5w, fc5b, lng, lnb, p5a, fc6w, fc6b, out);
}

// round 14
// speedup vs baseline: 1.1342x; 1.0562x over previous
#include <cuda_runtime.h>
#include <cuda_fp16.h>
#include <math.h>

#define N 4096
#define NN (4096ULL*4096ULL)
#define HROWS 2049            // stored spectral rows (hermitian half + nyquist)
#define TSTRIDE 2064          // padded row stride of transposed buffer

// ---------------- scratch ----------------
__device__ __half2 g_bufA[(size_t)HROWS * N];        // 33.6 MB: row-IFFT of hermitianized spectrum
__device__ __half2 g_bufB[(size_t)N * TSTRIDE];      // 33.8 MB: transposed [4096][2049(+pad)]
__device__ __half  g_imgh[NN];                       // 32 MB: spatial image * 4096 (fp16, TRANSPOSED)
__device__ float   g_c1[1365*1365];
__device__ float   g_c2[455*455];
__device__ float   g_c3[151*151];
__device__ float2  g_tw[1024];                       // W[k] = exp(+2*pi*i*k/4096)

// ---------------- complex helpers ----------------
__device__ __forceinline__ float2 cmul(float2 a, float2 b) {
    return make_float2(fmaf(a.x, b.x, -a.y * b.y), fmaf(a.x, b.y, a.y * b.x));
}
__device__ __forceinline__ float2 cadd(float2 a, float2 b) { return make_float2(a.x + b.x, a.y + b.y); }
__device__ __forceinline__ float2 csub(float2 a, float2 b) { return make_float2(a.x - b.x, a.y - b.y); }
__device__ __forceinline__ float2 cmuli(float2 z) { return make_float2(-z.y, z.x); }

__device__ __forceinline__ int SW(int i) { return i ^ ((i >> 4) & 15); }

// ---------------- fast atan2 ----------------
__device__ __forceinline__ float fast_atan2f(float y, float x)
{
    float ax = fabsf(x), ay = fabsf(y);
    float mx = fmaxf(ax, ay);
    float mn = fminf(ax, ay);
    float r  = __fdividef(mn, mx);
    float s  = r * r;
    float p  =             -0.0117212f;
    p = fmaf(p, s,  0.05265332f);
    p = fmaf(p, s, -0.11643287f);
    p = fmaf(p, s,  0.19354346f);
    p = fmaf(p, s, -0.33262347f);
    p = fmaf(p, s,  0.99997726f);
    float a = p * r;
    a = (ay > ax) ? (1.5707963267948966f - a) : a;
    a = (x < 0.0f) ? (3.1415926535897932f - a) : a;
    return (y < 0.0f) ? -a : a;
}

// ---------------- twiddle init ----------------
__global__ void twiddle_init() {
    int k = threadIdx.x;
    float sp, cp;
    sincospif(2.0f * (float)k / 4096.0f, &sp, &cp);
    g_tw[k] = make_float2(cp, sp);
}

// ---------------- register radix-8 inverse butterfly (serial twiddle chain) ----------------
template<bool TW>
__device__ __forceinline__ void bfly8(float2 x[8], int ps)
{
    const float R8 = 0.70710678118654752f;
    float2 apc = cadd(x[0], x[4]), amc = csub(x[0], x[4]);
    float2 bpd = cadd(x[2], x[6]), bmd = csub(x[2], x[6]);
    float2 E0 = cadd(apc, bpd);
    float2 E1 = cadd(amc, cmuli(bmd));
    float2 E2 = csub(apc, bpd);
    float2 E3 = csub(amc, cmuli(bmd));

    float2 opc = cadd(x[1], x[5]), omc = csub(x[1], x[5]);
    float2 ppd = cadd(x[3], x[7]), pmd = csub(x[3], x[7]);
    float2 O0 = cadd(opc, ppd);
    float2 O1 = cadd(omc, cmuli(pmd));
    float2 O2 = csub(opc, ppd);
    float2 O3 = csub(omc, cmuli(pmd));

    float2 T1 = cmul(make_float2( R8, R8), O1);
    float2 T2 = cmuli(O2);
    float2 T3 = cmul(make_float2(-R8, R8), O3);

    x[0] = cadd(E0, O0); x[4] = csub(E0, O0);
    x[1] = cadd(E1, T1); x[5] = csub(E1, T1);
    x[2] = cadd(E2, T2); x[6] = csub(E2, T2);
    x[3] = cadd(E3, T3); x[7] = csub(E3, T3);

    if (TW) {
        float2 w1 = g_tw[ps];
        float2 w2 = cmul(w1, w1);
        float2 w3 = cmul(w2, w1);
        float2 w4 = cmul(w2, w2);
        float2 w5 = cmul(w3, w2);
        float2 w6 = cmul(w3, w3);
        float2 w7 = cmul(w4, w3);
        x[1] = cmul(w1, x[1]); x[2] = cmul(w2, x[2]); x[3] = cmul(w3, x[3]);
        x[4] = cmul(w4, x[4]); x[5] = cmul(w5, x[5]); x[6] = cmul(w6, x[6]);
        x[7] = cmul(w7, x[7]);
    }
}

// ---------------- smem in-place stage ----------------
template<int S>
__device__ __forceinline__ void stage8_ip(float2* __restrict__ buf, int t)
{
    const int q  = t & (S - 1);
    const int ps = t - q;
    float2 x[8];
#pragma unroll
    for (int k = 0; k < 8; k++) x[k] = buf[SW(t + 512 * k)];
    bfly8<true>(x, ps);
    __syncthreads();
    const int ob = q + 8 * ps;
#pragma unroll
    for (int m = 0; m < 8; m++) buf[SW(ob + m * S)] = x[m];
    __syncthreads();
}

// elementwise spectrum math for one point
__device__ __forceinline__ float2 spec_point(float a, float b, float mkv, float pkv)
{
    float s2 = fmaf(a, a, b * b);
    float m = s2 * rsqrtf(fmaxf(s2, 1e-37f)) * mkv;
    float p = fast_atan2f(b, a) * pkv;
    float sp, cp;
    __sincosf(p, &sp, &cp);
    return make_float2(m * cp, m * sp);
}

// ---------------- pass 1: hermitianize in-place (fp32 RMW) + row IFFT, rows 0..2048 ----------------
__global__ void __launch_bounds__(512, 3)
fft_pass1(const float* __restrict__ xr, const float* __restrict__ xi,
          const float* __restrict__ mk, const float* __restrict__ pk)
{
    extern __shared__ float2 sm[];
    float2* s0 = sm;                          // 32 KB fp32 FFT buffer
    const int row = blockIdx.x;               // 0..2048
    const int rB  = (4096 - row) & 4095;      // paired row
    const int t   = threadIdx.x;

    const float4* xr4 = (const float4*)xr;
    const float4* xi4 = (const float4*)xi;
    const float4* mk4 = (const float4*)mk;
    const float4* pk4 = (const float4*)pk;

    // ---- phase 1: row `row` -> s0[idx] = C_A[idx]  (fp32, unhalved)
    {
        const int baseA = row * (N / 4);
#pragma unroll
        for (int e = 0; e < 2; e++) {
            int i4 = t + 512 * e;
            float4 ar = xr4[baseA + i4];
            float4 br = xi4[baseA + i4];
            float4 mr = mk4[baseA + i4];
            float4 pr = pk4[baseA + i4];
            float av[4] = {ar.x, ar.y, ar.z, ar.w};
            float bv[4] = {br.x, br.y, br.z, br.w};
            float mv[4] = {mr.x, mr.y, mr.z, mr.w};
            float pv[4] = {pr.x, pr.y, pr.z, pr.w};
#pragma unroll
            for (int j = 0; j < 4; j++) {
                int idx = 4 * i4 + j;
                s0[SW(idx)] = spec_point(av[j], bv[j], mv[j], pv[j]);
            }
        }
    }
    __syncthreads();

    // ---- phase 2: row rB -> RMW combine: s0[r] = 0.5*(s0[r] + conj(C_B[idx])), r=(4096-idx)&4095
    {
        const int baseB = rB * (N / 4);
#pragma unroll
        for (int e = 0; e < 2; e++) {
            int i4 = t + 512 * e;
            float4 ar = xr4[baseB + i4];
            float4 br = xi4[baseB + i4];
            float4 mr = mk4[baseB + i4];
            float4 pr = pk4[baseB + i4];
            float av[4] = {ar.x, ar.y, ar.z, ar.w};
            float bv[4] = {br.x, br.y, br.z, br.w};
            float mv[4] = {mr.x, mr.y, mr.z, mr.w};
            float pv[4] = {pr.x, pr.y, pr.z, pr.w};
#pragma unroll
            for (int j = 0; j < 4; j++) {
                int idx = 4 * i4 + j;
                float2 c = spec_point(av[j], bv[j], mv[j], pv[j]);
                int r = SW((4096 - idx) & 4095);
                float2 old = s0[r];
                s0[r] = make_float2(0.5f * (old.x + c.x), 0.5f * (old.y - c.y));
            }
        }
    }
    __syncthreads();

    stage8_ip<1>(s0, t);
    stage8_ip<8>(s0, t);
    stage8_ip<64>(s0, t);

    float2 x[8];
#pragma unroll
    for (int k = 0; k < 8; k++) x[k] = s0[SW(t + 512 * k)];
    bfly8<false>(x, 0);
    const size_t base = (size_t)row * N;
#pragma unroll
    for (int m = 0; m < 8; m++)
        g_bufA[base + t + 512 * m] = __float22half2_rn(x[m]);
}

// ---------------- fp16 transpose: [2049][4096] -> [4096][TSTRIDE] ----------------
__global__ void __launch_bounds__(256)
transpose_c()
{
    __shared__ __half2 tile[32][33];
    int x  = blockIdx.x * 32 + threadIdx.x;   // input col
    int y0 = blockIdx.y * 32;                 // input row base
#pragma unroll
    for (int j = threadIdx.y; j < 32; j += 8) {
        int r = y0 + j;
        if (r < HROWS)
            tile[j][threadIdx.x] = g_bufA[(size_t)r * N + x];
    }
    __syncthreads();
    int x2 = blockIdx.y * 32 + threadIdx.x;   // output col (= input row)
    int y2 = blockIdx.x * 32;                 // output row base (= input col)
#pragma unroll
    for (int j = threadIdx.y; j < 32; j += 8) {
        if (x2 < HROWS)
            g_bufB[(size_t)(y2 + j) * TSTRIDE + x2] = tile[threadIdx.x][j];
    }
}

// ---------------- pass 2: hermitian columns, two per FFT, direct mirrored gmem reads ----------------
__global__ void __launch_bounds__(512, 3)
fft_pass2()
{
    extern __shared__ float2 sm[];
    float2* s0 = sm;                               // 32 KB fp32 FFT buffer
    const int p = blockIdx.x;                      // column pair: n2 = 2p, 2p+1
    const int t = threadIdx.x;

    const __half2* rowB1 = g_bufB + (size_t)(2 * p)     * TSTRIDE;
    const __half2* rowB2 = g_bufB + (size_t)(2 * p + 1) * TSTRIDE;

    float2 x[8];
#pragma unroll
    for (int k = 0; k < 8; k++) {
        int idx = t + 512 * k;
        float2 z1, z2;
        if (idx <= 2048) {
            z1 = __half22float2(rowB1[idx]);
            z2 = __half22float2(rowB2[idx]);
        } else {
            int ridx = 4096 - idx;
            z1 = __half22float2(rowB1[ridx]); z1.y = -z1.y;
            z2 = __half22float2(rowB2[ridx]); z2.y = -z2.y;
        }
        x[k] = make_float2(z1.x - z2.y, z1.y + z2.x);
    }
    bfly8<true>(x, t);
#pragma unroll
    for (int m = 0; m < 8; m++) s0[SW(8 * t + m)] = x[m];
    __syncthreads();

    stage8_ip<8>(s0, t);
    stage8_ip<64>(s0, t);

#pragma unroll
    for (int k = 0; k < 8; k++) x[k] = s0[SW(t + 512 * k)];
    bfly8<false>(x, 0);
    const float scale = 1.0f / 4096.0f;
    const float sg = (t & 1) ? -scale : scale;
    const size_t base1 = (size_t)(2 * p)     * N;
    const size_t base2 = (size_t)(2 * p + 1) * N;
#pragma unroll
    for (int m = 0; m < 8; m++) {
        int n = t + 512 * m;
        g_imgh[base1 + n] = __float2half(x[m].x * sg);
        g_imgh[base2 + n] = __float2half(x[m].y * -sg);
    }
}

// ---------------- conv1 (half input, half2-vectorized, 2 outputs/thread) ----------------
__global__ void __launch_bounds__(256)
conv1_h2(const __half* __restrict__ in, float* __restrict__ out,
         const float* __restrict__ cw, const float* __restrict__ cb,
         const float* __restrict__ bg, const float* __restrict__ bb,
         const float* __restrict__ bm, const float* __restrict__ bv,
         const float* __restrict__ pa, float wscale)
{
    const int Win = 4096, Wout = 1365, Hout = 1365;
    int u = blockIdx.x * blockDim.x + threadIdx.x;   // output pair index
    int i = blockIdx.y * blockDim.y + threadIdx.y;
    int j0 = 2 * u;
    if (i >= Hout || j0 >= Wout) return;
    float w[9];
#pragma unroll
    for (int dy = 0; dy < 3; dy++)
#pragma unroll
        for (int dx = 0; dx < 3; dx++)
            w[dy * 3 + dx] = __ldg(&cw[dx * 3 + dy]) * wscale;   // transposed weight, layer 0
    float rs = rsqrtf(__ldg(&bv[0]) + 1e-5f);
    float gg = __ldg(&bg[0]);
    float sc = gg * rs;
    float sh = __ldg(&bb[0]) - gg * __ldg(&bm[0]) * rs;
    float cbv = __ldg(&cb[0]);
    float al  = __ldg(&pa[0]);

    const __half2* base = (const __half2*)(in + (size_t)(3 * i) * Win) + 3 * u;
    float acc0 = 0.0f, acc1 = 0.0f;
#pragma unroll
    for (int dy = 0; dy < 3; dy++) {
        const __half2* r = base + (size_t)dy * (Win / 2);
        float2 p0 = __half22float2(r[0]);
        float2 p1 = __half22float2(r[1]);
        float2 p2 = __half22float2(r[2]);
        acc0 = fmaf(p0.x, w[dy*3+0], acc0);
        acc0 = fmaf(p0.y, w[dy*3+1], acc0);
        acc0 = fmaf(p1.x, w[dy*3+2], acc0);
        acc1 = fmaf(p1.y, w[dy*3+0], acc1);
        acc1 = fmaf(p2.x, w[dy*3+1], acc1);
        acc1 = fmaf(p2.y, w[dy*3+2], acc1);
    }
    acc0 = fmaf(acc0 + cbv, sc, sh);
    acc1 = fmaf(acc1 + cbv, sc, sh);
    acc0 = (acc0 >= 0.0f) ? acc0 : al * acc0;
    acc1 = (acc1 >= 0.0f) ? acc1 : al * acc1;
    size_t ob = (size_t)i * Wout + j0;
    out[ob] = acc0;
    if (j0 + 1 < Wout) out[ob + 1] = acc1;
}

// ---------------- generic conv 3x3 stride 3 + bias + BN + PReLU (fp32 input) ----------------
__device__ __forceinline__ float conv_point(const float* __restrict__ in, int Win,
                                            int i, int j, const float* w,
                                            float cb, float sc, float sh, float al)
{
    const float* r0 = in + (size_t)(3 * i) * Win + 3 * j;
    float acc = 0.0f;
#pragma unroll
    for (int dy = 0; dy < 3; dy++)
#pragma unroll
        for (int dx = 0; dx < 3; dx++)
            acc = fmaf(r0[(size_t)dy * Win + dx], w[dy * 3 + dx], acc);
    acc += cb;
    acc = fmaf(acc, sc, sh);
    return (acc >= 0.0f) ? acc : al * acc;
}

__global__ void __launch_bounds__(256)
conv_bn_prelu(const float* __restrict__ in, float* __restrict__ out,
              int Win, int Wout, int Hout,
              const float* __restrict__ cw, const float* __restrict__ cb,
              const float* __restrict__ bg, const float* __restrict__ bb,
              const float* __restrict__ bm, const float* __restrict__ bv,
              const float* __restrict__ pa, int layer)
{
    int j = blockIdx.x * blockDim.x + threadIdx.x;
    int i = blockIdx.y * blockDim.y + threadIdx.y;
    if (i >= Hout || j >= Wout) return;
    const float* wb = cw + layer * 9;
    float w[9];
#pragma unroll
    for (int dy = 0; dy < 3; dy++)
#pragma unroll
        for (int dx = 0; dx < 3; dx++)
            w[dy * 3 + dx] = __ldg(&wb[dx * 3 + dy]);   // transposed weight
    float rs = rsqrtf(__ldg(&bv[layer]) + 1e-5f);
    float gg = __ldg(&bg[layer]);
    float sc = gg * rs;
    float sh = __ldg(&bb[layer]) - gg * __ldg(&bm[layer]) * rs;
    out[(size_t)i * Wout + j] =
        conv_point(in, Win, i, j, w, __ldg(&cb[layer]), sc, sh, __ldg(&pa[layer]));
}

// ---------------- fused tail ----------------
__global__ void __launch_bounds__(256, 1)
tail_kernel(const float* __restrict__ c3,
            const float* __restrict__ cw, const float* __restrict__ cbv,
            const float* __restrict__ bg, const float* __restrict__ bb,
            const float* __restrict__ bm, const float* __restrict__ bv,
            const float* __restrict__ pa,
            const float* __restrict__ fc5w, const float* __restrict__ fc5b,
            const float* __restrict__ lng,  const float* __restrict__ lnb,
            const float* __restrict__ p5a,
            const float* __restrict__ fc6w, const float* __restrict__ fc6b,
            float* __restrict__ out)
{
    __shared__ float c4s[2500];
    __shared__ float c5s[256];
    __shared__ float h[82];
    __shared__ float mu_s, rstd_s;
    const int t = threadIdx.x;

    {
        const int layer = 3;
        float w[9];
#pragma unroll
        for (int dy = 0; dy < 3; dy++)
#pragma unroll
            for (int dx = 0; dx < 3; dx++)
                w[dy * 3 + dx] = cw[layer * 9 + dx * 3 + dy];
        float rs = rsqrtf(bv[layer] + 1e-5f);
        float sc = bg[layer] * rs;
        float sh = bb[layer] - bg[layer] * bm[layer] * rs;
        for (int o = t; o < 2500; o += 256) {
            int i = o / 50, j = o % 50;
            c4s[o] = conv_point(c3, 151, i, j, w, cbv[layer], sc, sh, pa[layer]);
        }
    }
    __syncthreads();

    {
        const int layer = 4;
        float w[9];
#pragma unroll
        for (int dy = 0; dy < 3; dy++)
#pragma unroll
            for (int dx = 0; dx < 3; dx++)
                w[dy * 3 + dx] = cw[layer * 9 + dx * 3 + dy];
        float rs = rsqrtf(bv[layer] + 1e-5f);
        float sc = bg[layer] * rs;
        float sh = bb[layer] - bg[layer] * bm[layer] * rs;
        if (t < 256) {
            int i = t >> 4, j = t & 15;
            c5s[t] = conv_point(c4s, 50, i, j, w, cbv[layer], sc, sh, pa[layer]);
        }
    }
    __syncthreads();

    for (int o = t; o < 82; o += 256) {
        float acc = fc5b[o];
        for (int v = 0; v < 256; v++) {
            int i = v >> 4, j = v & 15;
            acc = fmaf(c5s[j * 16 + i], fc5w[v * 82 + o], acc);
        }
        h[o] = acc;
    }
    __syncthreads();
    if (t == 0) {
        float mu = 0.0f;
        for (int o = 0; o < 82; o++) mu += h[o];
        mu *= (1.0f / 82.0f);
        float var = 0.0f;
        for (int o = 0; o < 82; o++) { float dd = h[o] - mu; var = fmaf(dd, dd, var); }
        var *= (1.0f / 82.0f);
        mu_s = mu;
        rstd_s = rsqrtf(var + 1e-5f);
    }
    __syncthreads();
    if (t < 5) {
        float alpha = p5a[0];
        float acc = fc6b[t];
        for (int k = 0; k < 82; k++) {
            float v = (h[k] - mu_s) * rstd_s * lng[k] + lnb[k];
            v = (v >= 0.0f) ? v : alpha * v;
            acc = fmaf(v, fc6w[k * 5 + t], acc);
        }
        out[t] = acc;
    }
}

// ---------------- launch ----------------
extern "C" void kernel_launch(void* const* d_in, const int* in_sizes, int n_in,
                              void* d_out, int out_size)
{
    const float* xr    = (const float*)d_in[0];
    const float* xi    = (const float*)d_in[1];
    const float* mk    = (const float*)d_in[2];
    const float* pk    = (const float*)d_in[3];
    const float* convw = (const float*)d_in[4];
    const float* convb = (const float*)d_in[5];
    const float* bng   = (const float*)d_in[6];
    const float* bnb   = (const float*)d_in[7];
    const float* bnm   = (const float*)d_in[8];
    const float* bnv   = (const float*)d_in[9];
    const float* pra   = (const float*)d_in[10];
    const float* fc5w  = (const float*)d_in[11];
    const float* fc5b  = (const float*)d_in[12];
    const float* lng   = (const float*)d_in[13];
    const float* lnb   = (const float*)d_in[14];
    const float* p5a   = (const float*)d_in[15];
    const float* fc6w  = (const float*)d_in[16];
    const float* fc6b  = (const float*)d_in[17];
    float* out = (float*)d_out;

    cudaFuncSetAttribute(fft_pass1, cudaFuncAttributeMaxDynamicSharedMemorySize, 32768);
    cudaFuncSetAttribute(fft_pass2, cudaFuncAttributeMaxDynamicSharedMemorySize, 32768);

    __half* imgh;
    float *c1, *c2, *c3;
    cudaGetSymbolAddress((void**)&imgh, g_imgh);
    cudaGetSymbolAddress((void**)&c1,  g_c1);
    cudaGetSymbolAddress((void**)&c2,  g_c2);
    cudaGetSymbolAddress((void**)&c3,  g_c3);

    twiddle_init<<<1, 1024>>>();
    fft_pass1<<<HROWS, 512, 32768>>>(xr, xi, mk, pk);
    transpose_c<<<dim3(128, 65), dim3(32, 8)>>>();
    fft_pass2<<<2048, 512, 32768>>>();

    dim3 cb(32, 8);
    conv1_h2<<<dim3((683 + 31) / 32, (1365 + 7) / 8), cb>>>(imgh, c1,
        convw, convb, bng, bnb, bnm, bnv, pra, 1.0f / 4096.0f);
    conv_bn_prelu<<<dim3((455 + 31) / 32, (455 + 7) / 8), cb>>>(c1, c2, 1365, 455, 455,
        convw, convb, bng, bnb, bnm, bnv, pra, 1);
    conv_bn_prelu<<<dim3((151 + 31) / 32, (151 + 7) / 8), cb>>>(c2, c3, 455, 151, 151,
        convw, convb, bng, bnb, bnm, bnv, pra, 2);

    tail_kernel<<<1, 256>>>(c3, convw, convb, bng, bnb, bnm, bnv, pra,
                            fc5w, fc5b, lng, lnb, p5a, fc6w, fc6b, out);
}